// round 14
// baseline (speedup 1.0000x reference)
#include <cuda_runtime.h>
#include <cuda_bf16.h>
#include <cstdint>

#define VOCAB  20000
#define TOPK   8
#define GLOVE  300
#define OUTC   100
#define NLAB   8
#define ROWS   16
#define NTOK   4096
#define FACT_PER_V (TOPK * 2 * GLOVE)   // 4800 floats = 19200 B
#define C4     75                        // float4s per 300-float row
#define TOK_PER_BLK 8
#define RS_BLOCKS  (VOCAB / 8)           // 2500 rowsum blocks (8 warps each)
#define WT_BLOCKS  ((GLOVE * OUTC + 255) / 256)   // 118 transpose blocks

// Static scratch
__device__ float g_S[VOCAB * GLOVE];     // per-vocab row-sum (24 MB)
__device__ float g_wt[GLOVE * OUTC];     // W transposed: Wt[c*100 + o]

// ---------------------------------------------------------------------------
// K1 (HBM roofline, measured 6.6 TB/s): row-sum ALL vocab entries, with the
// tiny W-transpose merged in as trailing grid blocks (rides free under the
// memory-bound stream; kills a whole launch + its tail).
// ---------------------------------------------------------------------------
__global__ __launch_bounds__(256) void k_rowsum_wt(const float* __restrict__ fact,
                                                   const float* __restrict__ W) {
    if (blockIdx.x >= RS_BLOCKS) {
        // ---- transpose W: 118 blocks, 30000 elements ----
        int i = (blockIdx.x - RS_BLOCKS) * 256 + threadIdx.x;
        if (i < GLOVE * OUTC) {
            int c = i / OUTC, o = i % OUTC;
            g_wt[i] = W[o * GLOVE + c];
        }
        return;
    }

    const int gw   = (blockIdx.x * 256 + threadIdx.x) >> 5;   // vocab entry
    const int lane = threadIdx.x & 31;

    const float4* __restrict__ f4 = (const float4*)(fact + (size_t)gw * FACT_PER_V);
    float4* __restrict__ s4 = (float4*)(g_S + (size_t)gw * GLOVE);

    float4 a0 = make_float4(0.f, 0.f, 0.f, 0.f);
    float4 a1 = a0, a2 = a0;
    const bool has2 = (lane < C4 - 64);

    #pragma unroll 4
    for (int r = 0; r < ROWS; r++) {
        const float4* row = f4 + r * C4;
        float4 x0 = __ldcs(row + lane);
        float4 x1 = __ldcs(row + 32 + lane);
        a0.x += x0.x; a0.y += x0.y; a0.z += x0.z; a0.w += x0.w;
        a1.x += x1.x; a1.y += x1.y; a1.z += x1.z; a1.w += x1.w;
        if (has2) {
            float4 x2 = __ldcs(row + 64 + lane);
            a2.x += x2.x; a2.y += x2.y; a2.z += x2.z; a2.w += x2.w;
        }
    }
    s4[lane]      = a0;
    s4[32 + lane] = a1;
    if (has2) s4[64 + lane] = a2;
}

// ---------------------------------------------------------------------------
// K2 (fused gather + GEMM): 512 blocks x 256 threads, 8 tokens per block.
// Phase A: warp w gathers T[token] = sum_{8 labels} S[label] into smem.
// Phase B: 100 threads (25 o-groups x 4 token-pairs), each thread does
//          2 tokens x 4 outputs: per k = 1 LDG.128 (Wt, L1-hot) + 2 LDS
//          (broadcast) + 8 FFMA. Halves LSU issue pressure vs R6; 8
//          independent FFMA chains per thread cover the 4-cyc latency.
// ---------------------------------------------------------------------------
__global__ __launch_bounds__(256) void k_fused(const int* __restrict__ labels,
                                               const float* __restrict__ bias,
                                               float* __restrict__ out) {
    __shared__ __align__(16) float smT[TOK_PER_BLK * GLOVE];   // 9.6 KB

    const int tid  = threadIdx.x;
    const int wid  = tid >> 5;
    const int lane = tid & 31;
    const int tok0 = blockIdx.x * TOK_PER_BLK;

    // ---- Phase A: gather (warp wid owns token tok0+wid) ----
    {
        const int token = tok0 + wid;
        int lab[NLAB];
        #pragma unroll
        for (int j = 0; j < NLAB; j++) lab[j] = labels[token * NLAB + j];

        const float4* __restrict__ S4 = (const float4*)g_S;
        float4* __restrict__ T4 = (float4*)(smT + wid * GLOVE);

        #pragma unroll
        for (int cb = 0; cb < 3; cb++) {
            const int c = lane + cb * 32;
            if (c < C4) {
                float4 acc = make_float4(0.f, 0.f, 0.f, 0.f);
                #pragma unroll
                for (int j = 0; j < NLAB; j++) {
                    float4 x = S4[(size_t)lab[j] * C4 + c];
                    acc.x += x.x; acc.y += x.y; acc.z += x.z; acc.w += x.w;
                }
                T4[c] = acc;
            }
        }
    }
    __syncthreads();

    // ---- Phase B: GEMM, 2 tokens per thread ----
    if (tid < 25 * (TOK_PER_BLK / 2)) {          // 100 threads
        const int o4 = tid % 25;                 // 4 outputs
        const int tg = tid / 25;                 // token pair (0..3)
        const float* __restrict__ T0 = smT + (tg * 2)     * GLOVE;
        const float* __restrict__ T1 = smT + (tg * 2 + 1) * GLOVE;
        const float4* __restrict__ W4 = (const float4*)g_wt;   // [300][25] f4

        float4 a0 = make_float4(0.f, 0.f, 0.f, 0.f);
        float4 a1 = a0;
        #pragma unroll 6
        for (int k = 0; k < GLOVE; k++) {
            float4 w = W4[k * 25 + o4];
            float t0 = T0[k];
            float t1 = T1[k];
            a0.x += w.x * t0; a0.y += w.y * t0; a0.z += w.z * t0; a0.w += w.w * t0;
            a1.x += w.x * t1; a1.y += w.y * t1; a1.z += w.z * t1; a1.w += w.w * t1;
        }

        const float sc = 1.0f / (NLAB * ROWS);
        float4 b4 = ((const float4*)bias)[o4];
        float4* __restrict__ out4 = (float4*)out;
        float4 r;
        r.x = a0.x * sc + b4.x; r.y = a0.y * sc + b4.y;
        r.z = a0.z * sc + b4.z; r.w = a0.w * sc + b4.w;
        out4[(size_t)(tok0 + tg * 2) * 25 + o4] = r;
        r.x = a1.x * sc + b4.x; r.y = a1.y * sc + b4.y;
        r.z = a1.z * sc + b4.z; r.w = a1.w * sc + b4.w;
        out4[(size_t)(tok0 + tg * 2 + 1) * 25 + o4] = r;
    }
}

// ---------------------------------------------------------------------------
extern "C" void kernel_launch(void* const* d_in, const int* in_sizes, int n_in,
                              void* d_out, int out_size) {
    const int*   labels = (const int*)d_in[0];    // [32,128,8] int32
    const float* fact   = (const float*)d_in[1];  // [20000,8,600] f32
    const float* W      = (const float*)d_in[2];  // [100,300] f32
    const float* bias   = (const float*)d_in[3];  // [100] f32
    float* out = (float*)d_out;                   // [32,128,100] f32

    k_rowsum_wt<<<RS_BLOCKS + WT_BLOCKS, 256>>>(fact, W);
    k_fused<<<NTOK / TOK_PER_BLK, 256>>>(labels, bias, out);
}